// round 1
// baseline (speedup 1.0000x reference)
#include <cuda_runtime.h>

#define DIM  64
#define MM_  64      // neighbors per node
#define NB   2048    // batch
#define LL   2       // hops
#define NREL 32

// Scratch (no dynamic allocation allowed)
__device__ float g_RpreT[DIM * NREL];        // [j][rel] : b1[j] + rel_emb[rel]·w1[j,64:128]
__device__ float g_waggT[3 * DIM * DIM];     // [k][j]   : wagg transposed
__device__ float g_side[2][NB][DIM];         // users / items side outputs

__device__ __forceinline__ float sigmoidf_(float x) {
    return 1.f / (1.f + expf(-x));
}

// ---------------------------------------------------------------------------
// Prep: fold b1 + relation half of layer-1 into a 32x64 table; transpose wagg.
// ---------------------------------------------------------------------------
__global__ void prep_kernel(const float* __restrict__ rel_emb,
                            const float* __restrict__ w1,
                            const float* __restrict__ b1,
                            const float* __restrict__ wagg) {
    int t = blockIdx.x * blockDim.x + threadIdx.x;
    if (t < DIM * NREL) {
        int j = t >> 5, rel = t & 31;
        float acc = b1[j];
        #pragma unroll 8
        for (int k = 0; k < DIM; k++)
            acc += rel_emb[rel * DIM + k] * w1[j * 2 * DIM + DIM + k];
        g_RpreT[j * NREL + rel] = acc;
    }
    if (t < 3 * DIM * DIM) {
        int j = t & 63, k = t >> 6;
        g_waggT[t] = wagg[j * 3 * DIM + k];
    }
}

// ---------------------------------------------------------------------------
// Main: one block = 2 (side,b) pairs; thread = one neighbor m (and one dim d).
// ---------------------------------------------------------------------------
__global__ void __launch_bounds__(128, 2)
side_kernel(const float* __restrict__ ent_emb,
            const float* __restrict__ rec_emb,
            const float* __restrict__ w1,
            const float* __restrict__ w2,
            const float* __restrict__ b2,
            const float* __restrict__ w3,
            const float* __restrict__ b3,
            const float* __restrict__ bagg,
            const int* __restrict__ u_ent,  const int* __restrict__ u_heads,
            const int* __restrict__ u_rels, const int* __restrict__ u_tails,
            const int* __restrict__ v_ent,  const int* __restrict__ v_heads,
            const int* __restrict__ v_rels, const int* __restrict__ v_tails) {
    const int side = blockIdx.y;
    const int tid  = threadIdx.x;
    const int sub  = tid >> 6;         // which of the 2 batches this block handles
    const int m    = tid & 63;         // neighbor index == output dim index
    const int b    = blockIdx.x * 2 + sub;

    const float* emb0 = side ? ent_emb : rec_emb;
    const int* ent    = side ? v_ent   : u_ent;
    const int* heads  = side ? v_heads : u_heads;
    const int* rels   = side ? v_rels  : u_rels;
    const int* tails  = side ? v_tails : u_tails;

    __shared__ float4 w1h4_s[DIM * 16];   // [j][q] head-half of w1 (16 KB)
    __shared__ float4 w2_4s [DIM * 16];   // [j][q] w2 (16 KB)
    __shared__ float  RpreT_s[DIM * NREL];// [j][rel] (8 KB)
    __shared__ float  w3_s[DIM], b2_s[DIM], bagg_s[DIM];
    __shared__ float  pi_s[2][MM_];
    __shared__ int    idx_s[2][MM_];
    __shared__ float  emb_s[2][3 * DIM];

    {
        float* w1h_f = (float*)w1h4_s;
        float* w2_f  = (float*)w2_4s;
        for (int i = tid; i < DIM * DIM; i += 128) {
            w1h_f[i] = w1[(i >> 6) * (2 * DIM) + (i & 63)];  // head half: cols 0..63
            w2_f[i]  = w2[i];
        }
        for (int i = tid; i < DIM * NREL; i += 128) RpreT_s[i] = g_RpreT[i];
        if (tid < DIM) { w3_s[tid] = w3[tid]; b2_s[tid] = b2[tid]; bagg_s[tid] = bagg[tid]; }
    }
    const float b3v = b3[0];

    // hop-0 entity indices
    idx_s[sub][m] = ent[b * MM_ + m];
    __syncthreads();

    // hop-0: e0[d] = mean over neighbors of emb0 row; thread d = m (coalesced)
    float e0 = 0.f;
    #pragma unroll 8
    for (int mm = 0; mm < MM_; mm++)
        e0 += emb0[(long)idx_s[sub][mm] * DIM + m];
    e0 *= (1.f / 64.f);

    float a_out[LL];

    #pragma unroll 1
    for (int l = 0; l < LL; l++) {
        const int off  = l * NB * MM_ + b * MM_ + m;
        const int head = heads[off];
        const int rel  = rels[off];
        const int tail = tails[off];

        // Gather this neighbor's head embedding into registers (16 x LDG.128)
        float4 h4[16];
        const float4* hp = (const float4*)(ent_emb + (long)head * DIM);
        #pragma unroll
        for (int q = 0; q < 16; q++) h4[q] = hp[q];

        // ---- layer 1: y1[j] = relu(Rpre[rel][j] + h · w1[j,0:64]) ----
        float y1[DIM];
        #pragma unroll
        for (int j = 0; j < DIM; j++) {
            float acc0 = RpreT_s[j * NREL + rel];
            float acc1 = 0.f;
            #pragma unroll
            for (int q = 0; q < 16; q += 2) {
                float4 wa = w1h4_s[j * 16 + q];
                float4 wb = w1h4_s[j * 16 + q + 1];
                acc0 += h4[q].x * wa.x + h4[q].y * wa.y + h4[q].z * wa.z + h4[q].w * wa.w;
                acc1 += h4[q+1].x * wb.x + h4[q+1].y * wb.y + h4[q+1].z * wb.z + h4[q+1].w * wb.w;
            }
            y1[j] = fmaxf(acc0 + acc1, 0.f);
        }

        // ---- layer 2 + 3 fused: pi = sigmoid(b3 + sum_j relu(b2[j]+y1·w2[j]) * w3[j]) ----
        float pia = b3v;
        #pragma unroll
        for (int j = 0; j < DIM; j++) {
            float acc0 = b2_s[j];
            float acc1 = 0.f;
            #pragma unroll
            for (int q = 0; q < 16; q += 2) {
                float4 wa = w2_4s[j * 16 + q];
                float4 wb = w2_4s[j * 16 + q + 1];
                acc0 += y1[4*q+0] * wa.x + y1[4*q+1] * wa.y + y1[4*q+2] * wa.z + y1[4*q+3] * wa.w;
                acc1 += y1[4*q+4] * wb.x + y1[4*q+5] * wb.y + y1[4*q+6] * wb.z + y1[4*q+7] * wb.w;
            }
            pia += fmaxf(acc0 + acc1, 0.f) * w3_s[j];
        }
        const float pi = sigmoidf_(pia);

        __syncthreads();           // previous users of pi_s / idx_s are done
        pi_s[sub][m]  = pi;
        idx_s[sub][m] = tail;
        __syncthreads();

        // softmax over the 64 neighbors (computed redundantly, deterministic order)
        float mx = -1e30f;
        #pragma unroll 8
        for (int mm = 0; mm < MM_; mm++) mx = fmaxf(mx, pi_s[sub][mm]);
        float se = 0.f;
        #pragma unroll 8
        for (int mm = 0; mm < MM_; mm++) se += expf(pi_s[sub][mm] - mx);
        const float inv = 1.f / se;

        // a[d] = sum_m softmax(pi)[m] * ent_emb[tail[m]][d]; thread d = m (coalesced)
        float av = 0.f;
        #pragma unroll 8
        for (int mm = 0; mm < MM_; mm++) {
            float wgt = expf(pi_s[sub][mm] - mx) * inv;
            av += wgt * ent_emb[(long)idx_s[sub][mm] * DIM + m];
        }
        a_out[l] = av;
    }

    // ---- aggregation: sigmoid([e0|a1|a2] @ wagg.T + bagg) ----
    __syncthreads();
    emb_s[sub][m]           = e0;
    emb_s[sub][DIM + m]     = a_out[0];
    emb_s[sub][2 * DIM + m] = a_out[1];
    __syncthreads();

    float acc = bagg_s[m];
    #pragma unroll 8
    for (int k = 0; k < 3 * DIM; k++)
        acc += emb_s[sub][k] * g_waggT[k * DIM + m];   // coalesced, L1-hot
    g_side[side][b][m] = sigmoidf_(acc);
}

// ---------------------------------------------------------------------------
// Combine: out[b] = sigmoid(users[b] · items[b]); one warp per b.
// ---------------------------------------------------------------------------
__global__ void combine_kernel(float* __restrict__ out) {
    int gw   = (blockIdx.x * blockDim.x + threadIdx.x) >> 5;
    int lane = threadIdx.x & 31;
    if (gw >= NB) return;
    float s = g_side[0][gw][lane]      * g_side[1][gw][lane]
            + g_side[0][gw][lane + 32] * g_side[1][gw][lane + 32];
    #pragma unroll
    for (int o = 16; o; o >>= 1) s += __shfl_down_sync(0xffffffffu, s, o);
    if (lane == 0) out[gw] = 1.f / (1.f + expf(-s));
}

extern "C" void kernel_launch(void* const* d_in, const int* in_sizes, int n_in,
                              void* d_out, int out_size) {
    const float* ent_emb = (const float*)d_in[0];
    const float* rec_emb = (const float*)d_in[1];
    const float* rel_emb = (const float*)d_in[2];
    const float* w1      = (const float*)d_in[3];
    const float* b1      = (const float*)d_in[4];
    const float* w2      = (const float*)d_in[5];
    const float* b2      = (const float*)d_in[6];
    const float* w3      = (const float*)d_in[7];
    const float* b3      = (const float*)d_in[8];
    const float* wagg    = (const float*)d_in[9];
    const float* bagg    = (const float*)d_in[10];
    const int*   u_ent   = (const int*)d_in[11];
    const int*   u_heads = (const int*)d_in[12];
    const int*   u_rels  = (const int*)d_in[13];
    const int*   u_tails = (const int*)d_in[14];
    const int*   v_ent   = (const int*)d_in[15];
    const int*   v_heads = (const int*)d_in[16];
    const int*   v_rels  = (const int*)d_in[17];
    const int*   v_tails = (const int*)d_in[18];

    prep_kernel<<<48, 256>>>(rel_emb, w1, b1, wagg);
    side_kernel<<<dim3(NB / 2, 2), 128>>>(ent_emb, rec_emb, w1, w2, b2, w3, b3, bagg,
                                          u_ent, u_heads, u_rels, u_tails,
                                          v_ent, v_heads, v_rels, v_tails);
    combine_kernel<<<NB / 8, 256>>>((float*)d_out);
}

// round 2
// speedup vs baseline: 3.0896x; 3.0896x over previous
#include <cuda_runtime.h>
#include <cuda_bf16.h>
#include <cstdint>

#define DIM  64
#define MM_  64
#define NB   2048
#define LL   2
#define NREL 32

// Scratch (no dynamic allocation allowed)
__device__ float g_Rpre[NREL * DIM];       // [rel][j] : b1[j] + rel_emb[rel]·w1[j,64:128]
__device__ float g_emb[2][NB][3 * DIM];    // [side][b][e0 | a0 | a1]
__device__ float g_side[2][NB][DIM];       // users / items side outputs

__device__ __forceinline__ float sigmoidf_(float x) {
    return 1.f / (1.f + __expf(-x));
}
__device__ __forceinline__ uint32_t smem_u32(const void* p) {
    return (uint32_t)__cvta_generic_to_shared(p);
}
__device__ __forceinline__ void ldm_x4(uint32_t& r0, uint32_t& r1, uint32_t& r2, uint32_t& r3, uint32_t a) {
    asm volatile("ldmatrix.sync.aligned.m8n8.x4.shared.b16 {%0,%1,%2,%3},[%4];\n"
                 : "=r"(r0), "=r"(r1), "=r"(r2), "=r"(r3) : "r"(a));
}
__device__ __forceinline__ void ldm_x2(uint32_t& r0, uint32_t& r1, uint32_t a) {
    asm volatile("ldmatrix.sync.aligned.m8n8.x2.shared.b16 {%0,%1},[%2];\n"
                 : "=r"(r0), "=r"(r1) : "r"(a));
}
__device__ __forceinline__ void mma_bf16(float* d, uint32_t a0, uint32_t a1, uint32_t a2, uint32_t a3,
                                         uint32_t b0, uint32_t b1) {
    asm volatile("mma.sync.aligned.m16n8k16.row.col.f32.bf16.bf16.f32 "
                 "{%0,%1,%2,%3},{%4,%5,%6,%7},{%8,%9},{%0,%1,%2,%3};\n"
                 : "+f"(d[0]), "+f"(d[1]), "+f"(d[2]), "+f"(d[3])
                 : "r"(a0), "r"(a1), "r"(a2), "r"(a3), "r"(b0), "r"(b1));
}

// ---------------------------------------------------------------------------
// Prep: Rpre[rel][j] = b1[j] + rel_emb[rel] · w1[j, 64:128]
// ---------------------------------------------------------------------------
__global__ void prep_kernel(const float* __restrict__ rel_emb,
                            const float* __restrict__ w1,
                            const float* __restrict__ b1) {
    int t = blockIdx.x * blockDim.x + threadIdx.x;   // 2048 threads: warp = one j
    int j = t >> 5, rel = t & 31;
    float acc = b1[j];
    const float* wr = w1 + j * 2 * DIM + DIM;
    const float* re = rel_emb + rel * DIM;
    #pragma unroll 16
    for (int k = 0; k < DIM; k++) acc = fmaf(re[k], wr[k], acc);
    g_Rpre[rel * DIM + j] = acc;
}

// ---------------------------------------------------------------------------
// Attention kernel: block = one (side, b). 128 threads, 4 warps.
// Warp w owns m-rows [16w, 16w+16). Layers 1&2 via bf16 mma.sync.
// ---------------------------------------------------------------------------
__global__ void __launch_bounds__(128, 4)
attn_kernel(const float* __restrict__ ent_emb, const float* __restrict__ rec_emb,
            const float* __restrict__ w1, const float* __restrict__ w2,
            const float* __restrict__ b2, const float* __restrict__ w3,
            const float* __restrict__ b3,
            const int* __restrict__ u_ent,  const int* __restrict__ u_heads,
            const int* __restrict__ u_rels, const int* __restrict__ u_tails,
            const int* __restrict__ v_ent,  const int* __restrict__ v_heads,
            const int* __restrict__ v_rels, const int* __restrict__ v_tails) {
    const int side = blockIdx.y;
    const int b    = blockIdx.x;
    const int tid  = threadIdx.x;
    const int lane = tid & 31;
    const int wid  = tid >> 5;

    __shared__ __nv_bfloat16 W1h_s[DIM][72];   // [j][k] head-half of w1
    __shared__ __nv_bfloat16 W2_s [DIM][72];   // [j][k]
    __shared__ __nv_bfloat16 A_s  [MM_][72];   // gathered head embeddings (bf16)
    __shared__ __nv_bfloat16 Y1_s [MM_][72];   // layer-1 activations (bf16)
    __shared__ float Rpre_s[NREL][65];
    __shared__ float b2_s[DIM], w3_s[DIM];
    __shared__ float pi_s[MM_], wgt_s[MM_];
    __shared__ int   rel_s[MM_], tail_s[MM_], e0i_s[MM_];
    __shared__ float part_s[2][DIM];

    const float* emb0 = side ? ent_emb : rec_emb;
    const int* ent    = side ? v_ent   : u_ent;
    const int* heads  = side ? v_heads : u_heads;
    const int* rels   = side ? v_rels  : u_rels;
    const int* tails  = side ? v_tails : u_tails;

    // stage weights
    for (int i = tid; i < DIM * DIM; i += 128) {
        int j = i >> 6, k = i & 63;
        W1h_s[j][k] = __float2bfloat16(w1[j * 2 * DIM + k]);
        W2_s[j][k]  = __float2bfloat16(w2[i]);
    }
    for (int i = tid; i < NREL * DIM; i += 128)
        Rpre_s[i >> 6][i & 63] = g_Rpre[i];
    if (tid < DIM) { b2_s[tid] = b2[tid]; w3_s[tid] = w3[tid]; }
    if (tid < MM_) e0i_s[tid] = ent[b * MM_ + tid];
    const float b3v = b3[0];
    __syncthreads();

    // ---- hop-0: e0[d] = mean over neighbors of emb0 row ----
    {
        int d = tid & 63, half = tid >> 6;
        float s = 0.f;
        #pragma unroll 8
        for (int mm = half * 32; mm < half * 32 + 32; mm++)
            s += emb0[(size_t)e0i_s[mm] * DIM + d];
        part_s[half][d] = s;
    }
    __syncthreads();
    if (tid < DIM)
        g_emb[side][b][tid] = (part_s[0][tid] + part_s[1][tid]) * (1.f / 64.f);

    // ldmatrix per-lane address components
    const int mbase   = wid * 16;
    const int aRow    = lane & 15;
    const int aColOff = (lane >> 4) << 3;          // 0 / 8
    const int bRow    = lane & 7;
    const int bColOff = ((lane >> 3) & 1) << 3;    // 0 / 8 (lanes >=16 mirror)
    const uint32_t baseA  = smem_u32(&A_s[0][0]);
    const uint32_t baseY  = smem_u32(&Y1_s[0][0]);
    const uint32_t baseW1 = smem_u32(&W1h_s[0][0]);
    const uint32_t baseW2 = smem_u32(&W2_s[0][0]);

    const int g  = lane >> 2;
    const int c2 = (lane & 3) * 2;
    const int m0 = mbase + g, m1 = m0 + 8;

    #pragma unroll 1
    for (int l = 0; l < LL; l++) {
        __syncthreads();   // previous hop fully done with A_s / rel_s / tail_s

        // ---- gather 64 head rows -> A_s (bf16), 2 threads per row ----
        {
            int row = tid >> 1, half = tid & 1;
            int hidx = heads[l * NB * MM_ + b * MM_ + row];
            const float4* src = (const float4*)(ent_emb + (size_t)hidx * DIM) + half * 8;
            #pragma unroll
            for (int q = 0; q < 8; q++) {
                float4 v = src[q];
                int col = half * 32 + q * 4;
                *(__nv_bfloat162*)&A_s[row][col]     = __floats2bfloat162_rn(v.x, v.y);
                *(__nv_bfloat162*)&A_s[row][col + 2] = __floats2bfloat162_rn(v.z, v.w);
            }
            if (tid < MM_) {
                rel_s[tid]  = rels [l * NB * MM_ + b * MM_ + tid];
                tail_s[tid] = tails[l * NB * MM_ + b * MM_ + tid];
            }
        }
        __syncthreads();

        // ---- layer 1: Y1 = relu(A @ W1h^T + Rpre[rel]) ----
        {
            float acc[8][4];
            #pragma unroll
            for (int nt = 0; nt < 8; nt++)
                #pragma unroll
                for (int q = 0; q < 4; q++) acc[nt][q] = 0.f;
            #pragma unroll
            for (int kk = 0; kk < 64; kk += 16) {
                uint32_t a0, a1, a2, a3;
                ldm_x4(a0, a1, a2, a3, baseA + ((mbase + aRow) * 72 + kk + aColOff) * 2);
                #pragma unroll
                for (int nt = 0; nt < 8; nt++) {
                    uint32_t b0, b1;
                    ldm_x2(b0, b1, baseW1 + ((nt * 8 + bRow) * 72 + kk + bColOff) * 2);
                    mma_bf16(acc[nt], a0, a1, a2, a3, b0, b1);
                }
            }
            int r0 = rel_s[m0], r1 = rel_s[m1];
            #pragma unroll
            for (int nt = 0; nt < 8; nt++) {
                int j = nt * 8 + c2;
                float v00 = fmaxf(acc[nt][0] + Rpre_s[r0][j],     0.f);
                float v01 = fmaxf(acc[nt][1] + Rpre_s[r0][j + 1], 0.f);
                float v10 = fmaxf(acc[nt][2] + Rpre_s[r1][j],     0.f);
                float v11 = fmaxf(acc[nt][3] + Rpre_s[r1][j + 1], 0.f);
                *(__nv_bfloat162*)&Y1_s[m0][j] = __floats2bfloat162_rn(v00, v01);
                *(__nv_bfloat162*)&Y1_s[m1][j] = __floats2bfloat162_rn(v10, v11);
            }
        }
        __syncthreads();

        // ---- layer 2 + 3 fused: pi[m] = sigmoid(b3 + sum_j relu(Y1·w2[j]+b2[j]) w3[j]) ----
        {
            float acc[8][4];
            #pragma unroll
            for (int nt = 0; nt < 8; nt++)
                #pragma unroll
                for (int q = 0; q < 4; q++) acc[nt][q] = 0.f;
            #pragma unroll
            for (int kk = 0; kk < 64; kk += 16) {
                uint32_t a0, a1, a2, a3;
                ldm_x4(a0, a1, a2, a3, baseY + ((mbase + aRow) * 72 + kk + aColOff) * 2);
                #pragma unroll
                for (int nt = 0; nt < 8; nt++) {
                    uint32_t b0, b1;
                    ldm_x2(b0, b1, baseW2 + ((nt * 8 + bRow) * 72 + kk + bColOff) * 2);
                    mma_bf16(acc[nt], a0, a1, a2, a3, b0, b1);
                }
            }
            float p0 = 0.f, p1 = 0.f;
            #pragma unroll
            for (int nt = 0; nt < 8; nt++) {
                int j = nt * 8 + c2;
                p0 += fmaxf(acc[nt][0] + b2_s[j],     0.f) * w3_s[j];
                p0 += fmaxf(acc[nt][1] + b2_s[j + 1], 0.f) * w3_s[j + 1];
                p1 += fmaxf(acc[nt][2] + b2_s[j],     0.f) * w3_s[j];
                p1 += fmaxf(acc[nt][3] + b2_s[j + 1], 0.f) * w3_s[j + 1];
            }
            p0 += __shfl_xor_sync(0xffffffffu, p0, 1);
            p0 += __shfl_xor_sync(0xffffffffu, p0, 2);
            p1 += __shfl_xor_sync(0xffffffffu, p1, 1);
            p1 += __shfl_xor_sync(0xffffffffu, p1, 2);
            if ((lane & 3) == 0) {
                pi_s[m0] = sigmoidf_(p0 + b3v);
                pi_s[m1] = sigmoidf_(p1 + b3v);
            }
        }
        __syncthreads();

        // ---- softmax over 64 neighbors (warp 0 only) ----
        if (wid == 0) {
            float v0 = pi_s[lane], v1 = pi_s[lane + 32];
            float mx = fmaxf(v0, v1);
            #pragma unroll
            for (int o = 16; o; o >>= 1) mx = fmaxf(mx, __shfl_xor_sync(0xffffffffu, mx, o));
            float e0v = __expf(v0 - mx), e1v = __expf(v1 - mx);
            float s = e0v + e1v;
            #pragma unroll
            for (int o = 16; o; o >>= 1) s += __shfl_xor_sync(0xffffffffu, s, o);
            float inv = 1.f / s;
            wgt_s[lane]      = e0v * inv;
            wgt_s[lane + 32] = e1v * inv;
        }
        __syncthreads();

        // ---- a[d] = sum_m wgt[m] * ent_emb[tail[m]][d] ----
        {
            int d = tid & 63, half = tid >> 6;
            float av = 0.f;
            #pragma unroll 8
            for (int mm = half * 32; mm < half * 32 + 32; mm++)
                av += wgt_s[mm] * ent_emb[(size_t)tail_s[mm] * DIM + d];
            part_s[half][d] = av;
        }
        __syncthreads();
        if (tid < DIM)
            g_emb[side][b][(1 + l) * DIM + tid] = part_s[0][tid] + part_s[1][tid];
    }
}

// ---------------------------------------------------------------------------
// Aggregation: g_side[row][j] = sigmoid(g_emb[row] · wagg[j] + bagg[j])
// block: 16 rows, waggT staged in smem [k][j] for conflict-free LDS.
// ---------------------------------------------------------------------------
__global__ void __launch_bounds__(128)
agg_kernel(const float* __restrict__ wagg, const float* __restrict__ bagg) {
    __shared__ float waggT_s[3 * DIM][DIM];   // 48 KB
    int tid = threadIdx.x;
    for (int i = tid; i < DIM * 3 * DIM; i += 128) {
        int j = i / (3 * DIM), k = i % (3 * DIM);
        waggT_s[k][j] = wagg[i];
    }
    int j = tid & 63, rh = tid >> 6;
    float bj = __ldg(&bagg[j]);
    __syncthreads();

    const float* embf = &g_emb[0][0][0];
    float* sidef = &g_side[0][0][0];
    int rowbase = blockIdx.x * 16;
    #pragma unroll 1
    for (int rr = 0; rr < 16; rr += 2) {
        int row = rowbase + rr + rh;
        const float* e = embf + (size_t)row * (3 * DIM);
        float acc = bj;
        #pragma unroll 12
        for (int k = 0; k < 3 * DIM; k++)
            acc = fmaf(e[k], waggT_s[k][j], acc);
        sidef[(size_t)row * DIM + j] = sigmoidf_(acc);
    }
}

// ---------------------------------------------------------------------------
// Combine: out[b] = sigmoid(users[b] · items[b]); one warp per b.
// ---------------------------------------------------------------------------
__global__ void combine_kernel(float* __restrict__ out) {
    int gw   = (blockIdx.x * blockDim.x + threadIdx.x) >> 5;
    int lane = threadIdx.x & 31;
    if (gw >= NB) return;
    float s = g_side[0][gw][lane]      * g_side[1][gw][lane]
            + g_side[0][gw][lane + 32] * g_side[1][gw][lane + 32];
    #pragma unroll
    for (int o = 16; o; o >>= 1) s += __shfl_down_sync(0xffffffffu, s, o);
    if (lane == 0) out[gw] = sigmoidf_(s);
}

extern "C" void kernel_launch(void* const* d_in, const int* in_sizes, int n_in,
                              void* d_out, int out_size) {
    const float* ent_emb = (const float*)d_in[0];
    const float* rec_emb = (const float*)d_in[1];
    const float* rel_emb = (const float*)d_in[2];
    const float* w1      = (const float*)d_in[3];
    const float* b1      = (const float*)d_in[4];
    const float* w2      = (const float*)d_in[5];
    const float* b2      = (const float*)d_in[6];
    const float* w3      = (const float*)d_in[7];
    const float* b3      = (const float*)d_in[8];
    const float* wagg    = (const float*)d_in[9];
    const float* bagg    = (const float*)d_in[10];
    const int*   u_ent   = (const int*)d_in[11];
    const int*   u_heads = (const int*)d_in[12];
    const int*   u_rels  = (const int*)d_in[13];
    const int*   u_tails = (const int*)d_in[14];
    const int*   v_ent   = (const int*)d_in[15];
    const int*   v_heads = (const int*)d_in[16];
    const int*   v_rels  = (const int*)d_in[17];
    const int*   v_tails = (const int*)d_in[18];

    prep_kernel<<<16, 128>>>(rel_emb, w1, b1);
    attn_kernel<<<dim3(NB, 2), 128>>>(ent_emb, rec_emb, w1, w2, b2, w3, b3,
                                      u_ent, u_heads, u_rels, u_tails,
                                      v_ent, v_heads, v_rels, v_tails);
    agg_kernel<<<4096 / 16, 128>>>(wagg, bagg);
    combine_kernel<<<NB / 8, 256>>>((float*)d_out);
}

// round 3
// speedup vs baseline: 4.0552x; 1.3125x over previous
#include <cuda_runtime.h>
#include <cuda_bf16.h>
#include <cstdint>

#define DIM  64
#define MM_  64
#define NB   2048
#define LL   2
#define NREL 32
#define BPB  8      // batches per block

// Scratch (no dynamic allocation allowed)
__device__ float         g_Rpre[NREL * DIM];     // [rel][j]
__device__ __nv_bfloat16 g_W1b[DIM * DIM];       // head half of w1, bf16
__device__ __nv_bfloat16 g_W2b[DIM * DIM];
__device__ float         g_waggT[3 * DIM * DIM]; // [k][j]
__device__ float         g_side[2][NB][DIM];

__device__ __forceinline__ float sigmoidf_(float x) {
    return 1.f / (1.f + __expf(-x));
}
__device__ __forceinline__ uint32_t smem_u32(const void* p) {
    return (uint32_t)__cvta_generic_to_shared(p);
}
__device__ __forceinline__ void ldm_x4(uint32_t& r0, uint32_t& r1, uint32_t& r2, uint32_t& r3, uint32_t a) {
    asm volatile("ldmatrix.sync.aligned.m8n8.x4.shared.b16 {%0,%1,%2,%3},[%4];\n"
                 : "=r"(r0), "=r"(r1), "=r"(r2), "=r"(r3) : "r"(a));
}
__device__ __forceinline__ void ldm_x2(uint32_t& r0, uint32_t& r1, uint32_t a) {
    asm volatile("ldmatrix.sync.aligned.m8n8.x2.shared.b16 {%0,%1},[%2];\n"
                 : "=r"(r0), "=r"(r1) : "r"(a));
}
__device__ __forceinline__ void mma_bf16(float* d, uint32_t a0, uint32_t a1, uint32_t a2, uint32_t a3,
                                         uint32_t b0, uint32_t b1) {
    asm volatile("mma.sync.aligned.m16n8k16.row.col.f32.bf16.bf16.f32 "
                 "{%0,%1,%2,%3},{%4,%5,%6,%7},{%8,%9},{%0,%1,%2,%3};\n"
                 : "+f"(d[0]), "+f"(d[1]), "+f"(d[2]), "+f"(d[3])
                 : "r"(a0), "r"(a1), "r"(a2), "r"(a3), "r"(b0), "r"(b1));
}

// ---------------------------------------------------------------------------
// Prep: Rpre table, bf16 weight tables, wagg transpose. One launch, 4096 thr.
// ---------------------------------------------------------------------------
__global__ void prep_kernel(const float* __restrict__ rel_emb,
                            const float* __restrict__ w1,
                            const float* __restrict__ b1,
                            const float* __restrict__ w2,
                            const float* __restrict__ wagg) {
    int t = blockIdx.x * blockDim.x + threadIdx.x;   // 4096 threads
    if (t < NREL * DIM) {                            // warp = one j
        int j = t >> 5, rel = t & 31;
        float acc = b1[j];
        const float* wr = w1 + j * 2 * DIM + DIM;
        const float* re = rel_emb + rel * DIM;
        #pragma unroll 16
        for (int k = 0; k < DIM; k++) acc = fmaf(re[k], wr[k], acc);
        g_Rpre[rel * DIM + j] = acc;
    }
    if (t < DIM * DIM) {
        g_W1b[t] = __float2bfloat16(w1[(t >> 6) * 2 * DIM + (t & 63)]);
        g_W2b[t] = __float2bfloat16(w2[t]);
    }
    for (int i = t; i < 3 * DIM * DIM; i += 4096) {
        int k = i >> 6, j = i & 63;
        g_waggT[i] = wagg[j * 3 * DIM + k];
    }
}

// ---------------------------------------------------------------------------
// Attention + aggregation: block = (side, 8 batches). 128 threads, 4 warps.
// ---------------------------------------------------------------------------
__global__ void __launch_bounds__(128, 4)
attn_kernel(const float* __restrict__ ent_emb, const float* __restrict__ rec_emb,
            const float* __restrict__ b2, const float* __restrict__ w3,
            const float* __restrict__ b3, const float* __restrict__ bagg,
            const int* __restrict__ u_ent,  const int* __restrict__ u_heads,
            const int* __restrict__ u_rels, const int* __restrict__ u_tails,
            const int* __restrict__ v_ent,  const int* __restrict__ v_heads,
            const int* __restrict__ v_rels, const int* __restrict__ v_tails) {
    const int side = blockIdx.y;
    const int tid  = threadIdx.x;
    const int lane = tid & 31;
    const int wid  = tid >> 5;

    __shared__ __nv_bfloat16 W1h_s[DIM][72];
    __shared__ __nv_bfloat16 W2_s [DIM][72];
    __shared__ __nv_bfloat16 A_s  [LL][MM_][72];   // head tiles; Y1 aliases in-place
    __shared__ __nv_bfloat16 Rpre_s[NREL][66];
    __shared__ float b2_s[DIM], w3_s[DIM], bagg_s[DIM];
    __shared__ float pi_s[MM_], wgt_s[MM_];
    __shared__ int   rel_s[LL][MM_], tail_s[LL][MM_], e0i_s[MM_];
    __shared__ float e0p_s[2][DIM], ap_s[LL][2][DIM], aggp_s[2][DIM], emb_s[3 * DIM];

    const float* emb0 = side ? ent_emb : rec_emb;
    const int* ent    = side ? v_ent   : u_ent;
    const int* heads  = side ? v_heads : u_heads;
    const int* rels   = side ? v_rels  : u_rels;
    const int* tails  = side ? v_tails : u_tails;

    // one-time staging (bf16 weights precomputed in prep)
    for (int i = tid; i < DIM * DIM; i += 128) {
        W1h_s[i >> 6][i & 63] = g_W1b[i];
        W2_s [i >> 6][i & 63] = g_W2b[i];
    }
    for (int i = tid; i < NREL * DIM; i += 128)
        Rpre_s[i >> 6][i & 63] = __float2bfloat16(g_Rpre[i]);
    if (tid < DIM) { b2_s[tid] = b2[tid]; w3_s[tid] = w3[tid]; bagg_s[tid] = bagg[tid]; }
    const float b3v = b3[0];

    // fragment addressing
    const int mbase   = wid * 16;
    const int aRow    = lane & 15;
    const int aColOff = (lane >> 4) << 3;
    const int bRow    = lane & 7;
    const int bColOff = ((lane >> 3) & 1) << 3;
    const uint32_t baseW1 = smem_u32(&W1h_s[0][0]);
    const uint32_t baseW2 = smem_u32(&W2_s[0][0]);
    const int g  = lane >> 2;
    const int c2 = (lane & 3) * 2;
    const int m0 = mbase + g, m1 = m0 + 8;

    #pragma unroll 1
    for (int it = 0; it < BPB; it++) {
        const int b = blockIdx.x * BPB + it;
        __syncthreads();                 // previous iteration fully done

        // ---- index loads + BOTH hops' head gathers (front-loaded, MLP=16) ----
        if (tid < MM_) {
            e0i_s[tid]     = ent  [b * MM_ + tid];
            rel_s [0][tid] = rels [b * MM_ + tid];
            rel_s [1][tid] = rels [NB * MM_ + b * MM_ + tid];
            tail_s[0][tid] = tails[b * MM_ + tid];
            tail_s[1][tid] = tails[NB * MM_ + b * MM_ + tid];
        }
        {
            int row = tid >> 1, half = tid & 1;
            #pragma unroll
            for (int l = 0; l < LL; l++) {
                int hidx = heads[l * NB * MM_ + b * MM_ + row];
                const float4* src = (const float4*)(ent_emb + (size_t)hidx * DIM) + half * 8;
                #pragma unroll
                for (int q = 0; q < 8; q++) {
                    float4 v = src[q];
                    int col = half * 32 + q * 4;
                    *(__nv_bfloat162*)&A_s[l][row][col]     = __floats2bfloat162_rn(v.x, v.y);
                    *(__nv_bfloat162*)&A_s[l][row][col + 2] = __floats2bfloat162_rn(v.z, v.w);
                }
            }
        }
        __syncthreads();

        // ---- hop-0 mean partials ----
        {
            int d = tid & 63, h2 = tid >> 6;
            float s = 0.f;
            #pragma unroll 8
            for (int mm = h2 * 32; mm < h2 * 32 + 32; mm++)
                s += emb0[(size_t)e0i_s[mm] * DIM + d];
            e0p_s[h2][d] = s;
        }

        // ---- hops ----
        #pragma unroll
        for (int l = 0; l < LL; l++) {
            const uint32_t baseA = smem_u32(&A_s[l][0][0]);

            // layer 1: Y1 = relu(A @ W1h^T + Rpre[rel]) -> written back into A_s[l] (warp-local rows)
            float acc[8][4];
            #pragma unroll
            for (int nt = 0; nt < 8; nt++)
                #pragma unroll
                for (int q = 0; q < 4; q++) acc[nt][q] = 0.f;
            #pragma unroll
            for (int kk = 0; kk < 64; kk += 16) {
                uint32_t a0, a1, a2, a3;
                ldm_x4(a0, a1, a2, a3, baseA + ((mbase + aRow) * 72 + kk + aColOff) * 2);
                #pragma unroll
                for (int nt = 0; nt < 8; nt++) {
                    uint32_t bb0, bb1;
                    ldm_x2(bb0, bb1, baseW1 + ((nt * 8 + bRow) * 72 + kk + bColOff) * 2);
                    mma_bf16(acc[nt], a0, a1, a2, a3, bb0, bb1);
                }
            }
            {
                int r0 = rel_s[l][m0], r1 = rel_s[l][m1];
                #pragma unroll
                for (int nt = 0; nt < 8; nt++) {
                    int j = nt * 8 + c2;
                    float2 rp0 = __bfloat1622float2(*(const __nv_bfloat162*)&Rpre_s[r0][j]);
                    float2 rp1 = __bfloat1622float2(*(const __nv_bfloat162*)&Rpre_s[r1][j]);
                    float v00 = fmaxf(acc[nt][0] + rp0.x, 0.f);
                    float v01 = fmaxf(acc[nt][1] + rp0.y, 0.f);
                    float v10 = fmaxf(acc[nt][2] + rp1.x, 0.f);
                    float v11 = fmaxf(acc[nt][3] + rp1.y, 0.f);
                    *(__nv_bfloat162*)&A_s[l][m0][j] = __floats2bfloat162_rn(v00, v01);
                    *(__nv_bfloat162*)&A_s[l][m1][j] = __floats2bfloat162_rn(v10, v11);
                }
            }
            __syncwarp();

            // layer 2 + 3 fused
            float acc2[8][4];
            #pragma unroll
            for (int nt = 0; nt < 8; nt++)
                #pragma unroll
                for (int q = 0; q < 4; q++) acc2[nt][q] = 0.f;
            #pragma unroll
            for (int kk = 0; kk < 64; kk += 16) {
                uint32_t a0, a1, a2, a3;
                ldm_x4(a0, a1, a2, a3, baseA + ((mbase + aRow) * 72 + kk + aColOff) * 2);
                #pragma unroll
                for (int nt = 0; nt < 8; nt++) {
                    uint32_t bb0, bb1;
                    ldm_x2(bb0, bb1, baseW2 + ((nt * 8 + bRow) * 72 + kk + bColOff) * 2);
                    mma_bf16(acc2[nt], a0, a1, a2, a3, bb0, bb1);
                }
            }
            float p0 = 0.f, p1 = 0.f;
            #pragma unroll
            for (int nt = 0; nt < 8; nt++) {
                int j = nt * 8 + c2;
                p0 += fmaxf(acc2[nt][0] + b2_s[j],     0.f) * w3_s[j];
                p0 += fmaxf(acc2[nt][1] + b2_s[j + 1], 0.f) * w3_s[j + 1];
                p1 += fmaxf(acc2[nt][2] + b2_s[j],     0.f) * w3_s[j];
                p1 += fmaxf(acc2[nt][3] + b2_s[j + 1], 0.f) * w3_s[j + 1];
            }
            p0 += __shfl_xor_sync(0xffffffffu, p0, 1);
            p0 += __shfl_xor_sync(0xffffffffu, p0, 2);
            p1 += __shfl_xor_sync(0xffffffffu, p1, 1);
            p1 += __shfl_xor_sync(0xffffffffu, p1, 2);

            __syncthreads();   // previous hop's pi_s/wgt_s consumers are done
            if ((lane & 3) == 0) {
                pi_s[m0] = sigmoidf_(p0 + b3v);
                pi_s[m1] = sigmoidf_(p1 + b3v);
            }
            __syncthreads();

            // softmax over 64 neighbors (warp 0)
            if (wid == 0) {
                float v0 = pi_s[lane], v1 = pi_s[lane + 32];
                float mx = fmaxf(v0, v1);
                #pragma unroll
                for (int o = 16; o; o >>= 1) mx = fmaxf(mx, __shfl_xor_sync(0xffffffffu, mx, o));
                float e0v = __expf(v0 - mx), e1v = __expf(v1 - mx);
                float s = e0v + e1v;
                #pragma unroll
                for (int o = 16; o; o >>= 1) s += __shfl_xor_sync(0xffffffffu, s, o);
                float inv = 1.f / s;
                wgt_s[lane]      = e0v * inv;
                wgt_s[lane + 32] = e1v * inv;
            }
            __syncthreads();

            // weighted tail aggregation (coalesced gather)
            {
                int d = tid & 63, h2 = tid >> 6;
                float av = 0.f;
                #pragma unroll 8
                for (int mm = h2 * 32; mm < h2 * 32 + 32; mm++)
                    av += wgt_s[mm] * ent_emb[(size_t)tail_s[l][mm] * DIM + d];
                ap_s[l][h2][d] = av;
            }
        }

        // ---- fused aggregation layer ----
        __syncthreads();
        if (tid < 64) {
            emb_s[tid]       = (e0p_s[0][tid] + e0p_s[1][tid]) * (1.f / 64.f);
            emb_s[128 + tid] = ap_s[1][0][tid] + ap_s[1][1][tid];
        } else {
            int d = tid - 64;
            emb_s[64 + d]    = ap_s[0][0][d] + ap_s[0][1][d];
        }
        __syncthreads();
        {
            int j = tid & 63, h2 = tid >> 6;
            float acc = 0.f;
            const float* wt = g_waggT + (size_t)(h2 * 96) * DIM + j;
            #pragma unroll 12
            for (int k = 0; k < 96; k++)
                acc = fmaf(emb_s[h2 * 96 + k], wt[(size_t)k * DIM], acc);
            aggp_s[h2][j] = acc;
        }
        __syncthreads();
        if (tid < 64)
            g_side[side][b][tid] = sigmoidf_(aggp_s[0][tid] + aggp_s[1][tid] + bagg_s[tid]);
    }
}

// ---------------------------------------------------------------------------
// Combine: out[b] = sigmoid(users[b] · items[b]); one warp per b.
// ---------------------------------------------------------------------------
__global__ void combine_kernel(float* __restrict__ out) {
    int gw   = (blockIdx.x * blockDim.x + threadIdx.x) >> 5;
    int lane = threadIdx.x & 31;
    if (gw >= NB) return;
    float s = g_side[0][gw][lane]      * g_side[1][gw][lane]
            + g_side[0][gw][lane + 32] * g_side[1][gw][lane + 32];
    #pragma unroll
    for (int o = 16; o; o >>= 1) s += __shfl_down_sync(0xffffffffu, s, o);
    if (lane == 0) out[gw] = sigmoidf_(s);
}

extern "C" void kernel_launch(void* const* d_in, const int* in_sizes, int n_in,
                              void* d_out, int out_size) {
    const float* ent_emb = (const float*)d_in[0];
    const float* rec_emb = (const float*)d_in[1];
    const float* rel_emb = (const float*)d_in[2];
    const float* w1      = (const float*)d_in[3];
    const float* b1      = (const float*)d_in[4];
    const float* w2      = (const float*)d_in[5];
    const float* b2      = (const float*)d_in[6];
    const float* w3      = (const float*)d_in[7];
    const float* b3      = (const float*)d_in[8];
    const float* wagg    = (const float*)d_in[9];
    const float* bagg    = (const float*)d_in[10];
    const int*   u_ent   = (const int*)d_in[11];
    const int*   u_heads = (const int*)d_in[12];
    const int*   u_rels  = (const int*)d_in[13];
    const int*   u_tails = (const int*)d_in[14];
    const int*   v_ent   = (const int*)d_in[15];
    const int*   v_heads = (const int*)d_in[16];
    const int*   v_rels  = (const int*)d_in[17];
    const int*   v_tails = (const int*)d_in[18];

    prep_kernel<<<16, 256>>>(rel_emb, w1, b1, w2, wagg);
    attn_kernel<<<dim3(NB / BPB, 2), 128>>>(ent_emb, rec_emb, b2, w3, b3, bagg,
                                            u_ent, u_heads, u_rels, u_tails,
                                            v_ent, v_heads, v_rels, v_tails);
    combine_kernel<<<NB / 8, 256>>>((float*)d_out);
}

// round 4
// speedup vs baseline: 4.8957x; 1.2073x over previous
#include <cuda_runtime.h>
#include <cuda_bf16.h>
#include <cstdint>

#define DIM  64
#define MM_  64
#define NB   2048
#define LL   2
#define NREL 32
#define BPB  8      // batches per block

// Scratch (no dynamic allocation allowed)
__device__ float         g_Rpre[NREL * DIM];     // [rel][j]
__device__ __nv_bfloat16 g_W1b[DIM * DIM];       // head half of w1, bf16
__device__ __nv_bfloat16 g_W2b[DIM * DIM];
__device__ float         g_waggT[3 * DIM * DIM]; // [k][j]
__device__ float         g_side[2][NB][DIM];

__device__ __forceinline__ float sigmoidf_(float x) {
    return 1.f / (1.f + __expf(-x));
}
__device__ __forceinline__ uint32_t smem_u32(const void* p) {
    return (uint32_t)__cvta_generic_to_shared(p);
}
__device__ __forceinline__ void ldm_x4(uint32_t& r0, uint32_t& r1, uint32_t& r2, uint32_t& r3, uint32_t a) {
    asm volatile("ldmatrix.sync.aligned.m8n8.x4.shared.b16 {%0,%1,%2,%3},[%4];\n"
                 : "=r"(r0), "=r"(r1), "=r"(r2), "=r"(r3) : "r"(a));
}
__device__ __forceinline__ void mma_bf16(float* d, uint32_t a0, uint32_t a1, uint32_t a2, uint32_t a3,
                                         uint32_t b0, uint32_t b1) {
    asm volatile("mma.sync.aligned.m16n8k16.row.col.f32.bf16.bf16.f32 "
                 "{%0,%1,%2,%3},{%4,%5,%6,%7},{%8,%9},{%0,%1,%2,%3};\n"
                 : "+f"(d[0]), "+f"(d[1]), "+f"(d[2]), "+f"(d[3])
                 : "r"(a0), "r"(a1), "r"(a2), "r"(a3), "r"(b0), "r"(b1));
}

// ---------------------------------------------------------------------------
// Prep: blocks 0..31 -> Rpre[rel=blockIdx]; block 32 -> bf16 weights;
//       block 33 -> wagg transpose.  128 threads each.
// ---------------------------------------------------------------------------
__global__ void __launch_bounds__(128)
prep_kernel(const float* __restrict__ rel_emb,
            const float* __restrict__ w1,
            const float* __restrict__ b1,
            const float* __restrict__ w2,
            const float* __restrict__ wagg) {
    const int blk = blockIdx.x;
    const int t   = threadIdx.x;
    if (blk < NREL) {
        // thread (j = t>>1, half = t&1): partial dot over 32 k's
        int j = t >> 1, half = t & 1;
        const float* wr = w1 + j * 2 * DIM + DIM + half * 32;
        const float* re = rel_emb + blk * DIM + half * 32;
        float acc = 0.f;
        #pragma unroll
        for (int k = 0; k < 32; k++) acc = fmaf(re[k], wr[k], acc);
        acc += __shfl_xor_sync(0xffffffffu, acc, 1);
        if (half == 0) g_Rpre[blk * DIM + j] = acc + b1[j];
    } else if (blk == NREL) {
        for (int i = t; i < DIM * DIM; i += 128) {
            g_W1b[i] = __float2bfloat16(w1[(i >> 6) * 2 * DIM + (i & 63)]);
            g_W2b[i] = __float2bfloat16(w2[i]);
        }
    } else {
        for (int i = t; i < 3 * DIM * DIM; i += 128) {
            int k = i >> 6, j = i & 63;
            g_waggT[i] = wagg[j * 3 * DIM + k];
        }
    }
}

// ---------------------------------------------------------------------------
// Attention + aggregation: block = (side, 8 batches). 128 threads, 4 warps.
// ---------------------------------------------------------------------------
__global__ void __launch_bounds__(128, 4)
attn_kernel(const float* __restrict__ ent_emb, const float* __restrict__ rec_emb,
            const float* __restrict__ b2, const float* __restrict__ w3,
            const float* __restrict__ b3, const float* __restrict__ bagg,
            const int* __restrict__ u_ent,  const int* __restrict__ u_heads,
            const int* __restrict__ u_rels, const int* __restrict__ u_tails,
            const int* __restrict__ v_ent,  const int* __restrict__ v_heads,
            const int* __restrict__ v_rels, const int* __restrict__ v_tails) {
    const int side = blockIdx.y;
    const int tid  = threadIdx.x;
    const int lane = tid & 31;
    const int wid  = tid >> 5;

    __shared__ __nv_bfloat16 W1h_s[DIM][72];
    __shared__ __nv_bfloat16 W2_s [DIM][72];
    __shared__ __nv_bfloat16 A_s  [LL][MM_][72];   // head tiles; Y1 aliases in-place
    __shared__ __nv_bfloat16 Rpre_s[NREL][66];
    __shared__ float b2_s[DIM], w3_s[DIM], bagg_s[DIM];
    __shared__ float pi_s[MM_], wgt_s[MM_];
    __shared__ int   rel_s[LL][MM_], tail_s[LL][MM_], e0i_s[MM_];
    __shared__ float e0p_s[2][DIM], ap_s[LL][2][DIM], aggp_s[2][DIM], emb_s[3 * DIM];

    const float* emb0 = side ? ent_emb : rec_emb;
    const int* ent    = side ? v_ent   : u_ent;
    const int* heads  = side ? v_heads : u_heads;
    const int* rels   = side ? v_rels  : u_rels;
    const int* tails  = side ? v_tails : u_tails;

    // one-time staging
    for (int i = tid; i < DIM * DIM; i += 128) {
        W1h_s[i >> 6][i & 63] = g_W1b[i];
        W2_s [i >> 6][i & 63] = g_W2b[i];
    }
    for (int i = tid; i < NREL * DIM; i += 128)
        Rpre_s[i >> 6][i & 63] = __float2bfloat16(g_Rpre[i]);
    if (tid < DIM) { b2_s[tid] = b2[tid]; w3_s[tid] = w3[tid]; bagg_s[tid] = bagg[tid]; }
    const float b3v = b3[0];

    // fragment addressing
    const int mbase   = wid * 16;
    const int aRow    = lane & 15;
    const int aColOff = (lane >> 4) << 3;
    const int bRowOff = ((lane >> 4) << 3) + (lane & 7);  // pair-of-n-tiles x4 trick
    const int bKsel   = ((lane >> 3) & 1) << 3;
    const uint32_t baseW1 = smem_u32(&W1h_s[0][0]);
    const uint32_t baseW2 = smem_u32(&W2_s[0][0]);
    const int g  = lane >> 2;
    const int c2 = (lane & 3) * 2;
    const int m0 = mbase + g, m1 = m0 + 8;
    const int h2 = tid >> 6, dd = tid & 63;

    #pragma unroll 1
    for (int it = 0; it < BPB; it++) {
        const int b = blockIdx.x * BPB + it;
        __syncthreads();                 // previous iteration fully done

        // ---- index loads + BOTH hops' head gathers (front-loaded) ----
        if (tid < MM_) {
            e0i_s[tid]     = ent  [b * MM_ + tid];
            rel_s [0][tid] = rels [b * MM_ + tid];
            rel_s [1][tid] = rels [NB * MM_ + b * MM_ + tid];
            tail_s[0][tid] = tails[b * MM_ + tid];
            tail_s[1][tid] = tails[NB * MM_ + b * MM_ + tid];
        }
        {
            int row = tid >> 1, half = tid & 1;
            #pragma unroll
            for (int l = 0; l < LL; l++) {
                int hidx = heads[l * NB * MM_ + b * MM_ + row];
                const float4* src = (const float4*)(ent_emb + (size_t)hidx * DIM) + half * 8;
                #pragma unroll
                for (int q = 0; q < 8; q++) {
                    float4 v = src[q];
                    int col = half * 32 + q * 4;
                    *(__nv_bfloat162*)&A_s[l][row][col]     = __floats2bfloat162_rn(v.x, v.y);
                    *(__nv_bfloat162*)&A_s[l][row][col + 2] = __floats2bfloat162_rn(v.z, v.w);
                }
            }
        }
        __syncthreads();

        // ---- hop-0 mean partials (batched loads, MLP=16) ----
        {
            float s = 0.f;
            #pragma unroll
            for (int half = 0; half < 2; half++) {
                float v[16];
                #pragma unroll
                for (int i = 0; i < 16; i++)
                    v[i] = emb0[(size_t)e0i_s[h2 * 32 + half * 16 + i] * DIM + dd];
                #pragma unroll
                for (int i = 0; i < 16; i++) s += v[i];
            }
            e0p_s[h2][dd] = s;
        }

        // ---- hops ----
        #pragma unroll
        for (int l = 0; l < LL; l++) {
            const uint32_t baseA = smem_u32(&A_s[l][0][0]);

            // layer 1: Y1 = relu(A @ W1h^T + Rpre[rel]) -> in place (warp-local rows)
            float acc[8][4];
            #pragma unroll
            for (int nt = 0; nt < 8; nt++)
                #pragma unroll
                for (int q = 0; q < 4; q++) acc[nt][q] = 0.f;
            #pragma unroll
            for (int kk = 0; kk < 64; kk += 16) {
                uint32_t a0, a1, a2, a3;
                ldm_x4(a0, a1, a2, a3, baseA + ((mbase + aRow) * 72 + kk + aColOff) * 2);
                #pragma unroll
                for (int ntp = 0; ntp < 4; ntp++) {
                    uint32_t bb0, bb1, bb2, bb3;
                    ldm_x4(bb0, bb1, bb2, bb3,
                           baseW1 + ((ntp * 16 + bRowOff) * 72 + kk + bKsel) * 2);
                    mma_bf16(acc[2 * ntp],     a0, a1, a2, a3, bb0, bb1);
                    mma_bf16(acc[2 * ntp + 1], a0, a1, a2, a3, bb2, bb3);
                }
            }
            {
                int r0 = rel_s[l][m0], r1 = rel_s[l][m1];
                #pragma unroll
                for (int nt = 0; nt < 8; nt++) {
                    int j = nt * 8 + c2;
                    float2 rp0 = __bfloat1622float2(*(const __nv_bfloat162*)&Rpre_s[r0][j]);
                    float2 rp1 = __bfloat1622float2(*(const __nv_bfloat162*)&Rpre_s[r1][j]);
                    float v00 = fmaxf(acc[nt][0] + rp0.x, 0.f);
                    float v01 = fmaxf(acc[nt][1] + rp0.y, 0.f);
                    float v10 = fmaxf(acc[nt][2] + rp1.x, 0.f);
                    float v11 = fmaxf(acc[nt][3] + rp1.y, 0.f);
                    *(__nv_bfloat162*)&A_s[l][m0][j] = __floats2bfloat162_rn(v00, v01);
                    *(__nv_bfloat162*)&A_s[l][m1][j] = __floats2bfloat162_rn(v10, v11);
                }
            }
            __syncwarp();

            // layer 2 + 3 fused
            float acc2[8][4];
            #pragma unroll
            for (int nt = 0; nt < 8; nt++)
                #pragma unroll
                for (int q = 0; q < 4; q++) acc2[nt][q] = 0.f;
            #pragma unroll
            for (int kk = 0; kk < 64; kk += 16) {
                uint32_t a0, a1, a2, a3;
                ldm_x4(a0, a1, a2, a3, baseA + ((mbase + aRow) * 72 + kk + aColOff) * 2);
                #pragma unroll
                for (int ntp = 0; ntp < 4; ntp++) {
                    uint32_t bb0, bb1, bb2, bb3;
                    ldm_x4(bb0, bb1, bb2, bb3,
                           baseW2 + ((ntp * 16 + bRowOff) * 72 + kk + bKsel) * 2);
                    mma_bf16(acc2[2 * ntp],     a0, a1, a2, a3, bb0, bb1);
                    mma_bf16(acc2[2 * ntp + 1], a0, a1, a2, a3, bb2, bb3);
                }
            }
            float p0 = 0.f, p1 = 0.f;
            #pragma unroll
            for (int nt = 0; nt < 8; nt++) {
                int j = nt * 8 + c2;
                p0 += fmaxf(acc2[nt][0] + b2_s[j],     0.f) * w3_s[j];
                p0 += fmaxf(acc2[nt][1] + b2_s[j + 1], 0.f) * w3_s[j + 1];
                p1 += fmaxf(acc2[nt][2] + b2_s[j],     0.f) * w3_s[j];
                p1 += fmaxf(acc2[nt][3] + b2_s[j + 1], 0.f) * w3_s[j + 1];
            }
            p0 += __shfl_xor_sync(0xffffffffu, p0, 1);
            p0 += __shfl_xor_sync(0xffffffffu, p0, 2);
            p1 += __shfl_xor_sync(0xffffffffu, p1, 1);
            p1 += __shfl_xor_sync(0xffffffffu, p1, 2);

            __syncthreads();   // previous readers of pi_s done
            if ((lane & 3) == 0) {
                pi_s[m0] = sigmoidf_(p0 + b3v);
                pi_s[m1] = sigmoidf_(p1 + b3v);
            }
            __syncthreads();

            // softmax over 64 neighbors — redundantly in EVERY warp (value-identical
            // writes to wgt_s; each warp consumes only its own writes -> syncwarp).
            {
                float v0 = pi_s[lane], v1 = pi_s[lane + 32];
                float mx = fmaxf(v0, v1);
                #pragma unroll
                for (int o = 16; o; o >>= 1) mx = fmaxf(mx, __shfl_xor_sync(0xffffffffu, mx, o));
                float e0v = __expf(v0 - mx), e1v = __expf(v1 - mx);
                float s = e0v + e1v;
                #pragma unroll
                for (int o = 16; o; o >>= 1) s += __shfl_xor_sync(0xffffffffu, s, o);
                float inv = 1.f / s;
                wgt_s[lane]      = e0v * inv;
                wgt_s[lane + 32] = e1v * inv;
            }
            __syncwarp();

            // weighted tail aggregation (batched loads, MLP=16)
            {
                float av = 0.f;
                #pragma unroll
                for (int half = 0; half < 2; half++) {
                    float v[16];
                    #pragma unroll
                    for (int i = 0; i < 16; i++)
                        v[i] = ent_emb[(size_t)tail_s[l][h2 * 32 + half * 16 + i] * DIM + dd];
                    #pragma unroll
                    for (int i = 0; i < 16; i++)
                        av += wgt_s[h2 * 32 + half * 16 + i] * v[i];
                }
                ap_s[l][h2][dd] = av;
            }
        }

        // ---- fused aggregation layer ----
        __syncthreads();
        if (tid < 64) {
            emb_s[tid]       = (e0p_s[0][tid] + e0p_s[1][tid]) * (1.f / 64.f);
            emb_s[128 + tid] = ap_s[1][0][tid] + ap_s[1][1][tid];
        } else {
            emb_s[64 + dd]   = ap_s[0][0][dd] + ap_s[0][1][dd];
        }
        __syncthreads();
        {
            float acc = 0.f;
            const float* wt = g_waggT + (size_t)(h2 * 96) * DIM + dd;
            #pragma unroll 12
            for (int k = 0; k < 96; k++)
                acc = fmaf(emb_s[h2 * 96 + k], wt[(size_t)k * DIM], acc);
            aggp_s[h2][dd] = acc;
        }
        __syncthreads();
        if (tid < 64)
            g_side[side][b][tid] = sigmoidf_(aggp_s[0][tid] + aggp_s[1][tid] + bagg_s[tid]);
    }
}

// ---------------------------------------------------------------------------
// Combine: out[b] = sigmoid(users[b] · items[b]); one warp per b.
// ---------------------------------------------------------------------------
__global__ void combine_kernel(float* __restrict__ out) {
    int gw   = (blockIdx.x * blockDim.x + threadIdx.x) >> 5;
    int lane = threadIdx.x & 31;
    if (gw >= NB) return;
    float s = g_side[0][gw][lane]      * g_side[1][gw][lane]
            + g_side[0][gw][lane + 32] * g_side[1][gw][lane + 32];
    #pragma unroll
    for (int o = 16; o; o >>= 1) s += __shfl_down_sync(0xffffffffu, s, o);
    if (lane == 0) out[gw] = sigmoidf_(s);
}

extern "C" void kernel_launch(void* const* d_in, const int* in_sizes, int n_in,
                              void* d_out, int out_size) {
    const float* ent_emb = (const float*)d_in[0];
    const float* rec_emb = (const float*)d_in[1];
    const float* rel_emb = (const float*)d_in[2];
    const float* w1      = (const float*)d_in[3];
    const float* b1      = (const float*)d_in[4];
    const float* w2      = (const float*)d_in[5];
    const float* b2      = (const float*)d_in[6];
    const float* w3      = (const float*)d_in[7];
    const float* b3      = (const float*)d_in[8];
    const float* wagg    = (const float*)d_in[9];
    const float* bagg    = (const float*)d_in[10];
    const int*   u_ent   = (const int*)d_in[11];
    const int*   u_heads = (const int*)d_in[12];
    const int*   u_rels  = (const int*)d_in[13];
    const int*   u_tails = (const int*)d_in[14];
    const int*   v_ent   = (const int*)d_in[15];
    const int*   v_heads = (const int*)d_in[16];
    const int*   v_rels  = (const int*)d_in[17];
    const int*   v_tails = (const int*)d_in[18];

    prep_kernel<<<34, 128>>>(rel_emb, w1, b1, w2, wagg);
    attn_kernel<<<dim3(NB / BPB, 2), 128>>>(ent_emb, rec_emb, b2, w3, b3, bagg,
                                            u_ent, u_heads, u_rels, u_tails,
                                            v_ent, v_heads, v_rels, v_tails);
    combine_kernel<<<NB / 8, 256>>>((float*)d_out);
}